// round 5
// baseline (speedup 1.0000x reference)
#include <cuda_runtime.h>
#include <math.h>

// ---------------------------------------------------------------------------
// Problem constants
// ---------------------------------------------------------------------------
#define NB    16
#define CIN   128
#define COUT  128
#define HDIM  56
#define WDIM  56
#define LPIX  (HDIM * WDIM)          // 3136 pixels per image
#define KTOT  (9 * CIN)              // 1152 = GEMM K
#define NTOT  256                    // GEMM N = 2*COUT (cos/sin interleaved)
#define PADW  58
#define PADSZ (PADW * PADW)          // 3364
#define MTOT  (NB * LPIX)            // 50176 = GEMM M  (divisible by 128)

// GEMM tiling
#define BM 128
#define BN 128
#define BK 16
#define TM 8
#define TN 8
#define NKITERS (KTOT / BK)          // 72

#define PI_F      3.14159265358979323846f
#define HALFPI_F  1.57079632679489661923f
#define INVPI_F   0.31830988618379067154f

// ---------------------------------------------------------------------------
// Scratch (static device globals -- no allocation allowed)
// ---------------------------------------------------------------------------
__device__ float g_W[KTOT * NTOT];                 // folded weights, 1.18 MB
__device__ float g_xpad[NB * CIN * PADSZ];         // zero-padded input, 27.6 MB

// kernel-position byte offsets within padded 58-wide image: ki*58 + kj
__constant__ int c_koff[9] = {0, 1, 2, 58, 59, 60, 116, 117, 118};

// ---------------------------------------------------------------------------
// 1) Zero-pad x:  (b,c,56,56) -> (b,c,58,58) with 1-pixel zero border
// ---------------------------------------------------------------------------
__global__ void pad_kernel(const float* __restrict__ x) {
    int idx = blockIdx.x * blockDim.x + threadIdx.x;   // covers NB*CIN*PADSZ exactly
    int xx = idx % PADW;
    int t  = idx / PADW;
    int yy = t % PADW;
    int bc = t / PADW;
    float v = 0.0f;
    if (yy >= 1 && yy <= HDIM && xx >= 1 && xx <= WDIM)
        v = x[bc * LPIX + (yy - 1) * WDIM + (xx - 1)];
    g_xpad[idx] = v;
}

// ---------------------------------------------------------------------------
// 2) Fold cos/sin(b_k) into the weights.
//    g_W[kk][n]: kk = kpos*128 + c,  n = 2*o + s  (s=0 -> cos, s=1 -> sin)
//    weight layout: (1, 9, COUT, CIN);  b_k layout: (1, 9, 1, COUT, 1)
// ---------------------------------------------------------------------------
__global__ void wprep_kernel(const float* __restrict__ weight,
                             const float* __restrict__ b_k) {
    int kk = blockIdx.x;          // 0..1151
    int n  = threadIdx.x;         // 0..255
    int kp = kk >> 7;
    int c  = kk & 127;
    int o  = n >> 1;
    int s  = n & 1;
    float bkv = b_k[kp * COUT + o];
    float w   = weight[(kp * COUT + o) * CIN + c];
    float tr  = s ? sinf(bkv) : cosf(bkv);
    g_W[kk * NTOT + n] = w * tr;
}

// ---------------------------------------------------------------------------
// 3) Implicit-GEMM conv + fused phase epilogue.
//    M = 50176 pixels (global, images flattened), N = 128 per CTA (grid.y=2),
//    K = 1152. BMxBNxBK = 128x128x16, 256 threads, 8x8 micro-tile.
// ---------------------------------------------------------------------------
__global__ void __launch_bounds__(256, 2)
conv_main(const float* __restrict__ bias, float* __restrict__ out) {
    __shared__ __align__(16) float As[BK][BM];
    __shared__ __align__(16) float Bs[BK][BN];

    const int tid  = threadIdx.x;
    const int tile = blockIdx.x;           // 0..391
    const int n0   = blockIdx.y * BN;      // 0 or 128

    // ---- gather setup: each thread loads 8 K-values for ONE (m, n) pair ----
    // A element for load i: row m = tid&127 (constant), k-slot = (tid>>7) + 2*i
    const int mA   = tid & 127;
    const int kklA = tid >> 7;             // 0 or 1
    {
        // nothing
    }
    const int g    = tile * BM + mA;       // global pixel id, < 50176
    const int bimg = g / LPIX;
    const int l    = g - bimg * LPIX;
    const int y    = l / WDIM;
    const int x    = l - y * WDIM;
    const float* __restrict__ xbase =
        g_xpad + (size_t)bimg * (CIN * PADSZ) + y * PADW + x;
    const int nB = tid & 127;              // B column (constant per thread)

    float acc[TM][TN];
#pragma unroll
    for (int i = 0; i < TM; i++)
#pragma unroll
        for (int j = 0; j < TN; j++) acc[i][j] = 0.0f;

    float ra[8], rb[8];

    // ---- prologue: load & stage K-chunk 0 ----
#pragma unroll
    for (int i = 0; i < 8; i++) {
        int kk = kklA + 2 * i;
        int c  = kk & 127;
        int kp = kk >> 7;
        ra[i] = xbase[c * PADSZ + c_koff[kp]];
        rb[i] = g_W[kk * NTOT + n0 + nB];
    }
#pragma unroll
    for (int i = 0; i < 8; i++) {
        As[kklA + 2 * i][mA] = ra[i];
        Bs[kklA + 2 * i][nB] = rb[i];
    }
    __syncthreads();

    const int tm = tid >> 4;               // 0..15
    const int tn = tid & 15;               // 0..15

    // ---- main K loop, register double-buffered ----
    for (int it = 0; it < NKITERS; it++) {
        if (it + 1 < NKITERS) {
            const int kk0 = (it + 1) * BK;
#pragma unroll
            for (int i = 0; i < 8; i++) {
                int kk = kk0 + kklA + 2 * i;
                int c  = kk & 127;
                int kp = kk >> 7;
                ra[i] = xbase[c * PADSZ + c_koff[kp]];
                rb[i] = g_W[kk * NTOT + n0 + nB];
            }
        }
#pragma unroll
        for (int kb = 0; kb < BK; kb++) {
            float af[TM], bf[TN];
            *(float4*)&af[0] = *(const float4*)&As[kb][tm * TM];
            *(float4*)&af[4] = *(const float4*)&As[kb][tm * TM + 4];
            *(float4*)&bf[0] = *(const float4*)&Bs[kb][tn * TN];
            *(float4*)&bf[4] = *(const float4*)&Bs[kb][tn * TN + 4];
#pragma unroll
            for (int i = 0; i < TM; i++)
#pragma unroll
                for (int j = 0; j < TN; j++)
                    acc[i][j] = fmaf(af[i], bf[j], acc[i][j]);
        }
        __syncthreads();
        if (it + 1 < NKITERS) {
#pragma unroll
            for (int i = 0; i < 8; i++) {
                As[kklA + 2 * i][mA] = ra[i];
                Bs[kklA + 2 * i][nB] = rb[i];
            }
            __syncthreads();
        }
    }

    // ---- fused epilogue: phase computation + bias + store ----
    // thread owns m = tile*128 + tm*8 + i,  columns n = n0 + tn*8 + {0..7}
    // column pairing: even -> a (cos), odd -> bb (sin); o = (n>>1)
    const int obase = (n0 >> 1) + tn * 4;  // 4 output channels per thread
#pragma unroll
    for (int i = 0; i < TM; i++) {
        const int m_g = tile * BM + tm * TM + i;
        const int b   = m_g / LPIX;
        const int ll  = m_g - b * LPIX;
#pragma unroll
        for (int j = 0; j < 4; j++) {
            float a  = acc[i][2 * j];
            float bb = acc[i][2 * j + 1];
            const int o = obase + j;

            bool a_gt = a > 0.0f;
            bool b_gt = bb > 0.0f;
            bool eq   = (a_gt == b_gt);

            float theta = eq ? atanf(bb / (a + 1e-5f))
                             : -atanf(a / (bb + 1e-5f));
            float peak  = eq ? (a_gt ? HALFPI_F : -HALFPI_F)
                             : (b_gt ? 0.0f : -PI_F);
            theta = peak - theta;

            float st, ct;
            sincosf(theta, &st, &ct);
            float oval = fmaf(st, a, ct * bb) + bias[o];

            out[((size_t)(b * 2 * COUT + o)) * LPIX + ll]        = oval;
            out[((size_t)(b * 2 * COUT + COUT + o)) * LPIX + ll] = theta * INVPI_F;
        }
    }
}

// ---------------------------------------------------------------------------
// Launch: inputs per metadata order: x, weight, b_k, bias
// ---------------------------------------------------------------------------
extern "C" void kernel_launch(void* const* d_in, const int* in_sizes, int n_in,
                              void* d_out, int out_size) {
    const float* x      = (const float*)d_in[0];
    const float* weight = (const float*)d_in[1];
    const float* b_k    = (const float*)d_in[2];
    const float* bias   = (const float*)d_in[3];
    float* out          = (float*)d_out;

    // 1) pad input:  NB*CIN*PADSZ = 2048*3364 = 6,889,472 elements (/256 = 26912)
    pad_kernel<<<(NB * CIN * PADSZ) / 256, 256>>>(x);

    // 2) fold weights with cos/sin
    wprep_kernel<<<KTOT, NTOT>>>(weight, b_k);

    // 3) implicit GEMM conv + epilogue: grid (50176/128, 256/128)
    dim3 grid(MTOT / BM, NTOT / BN);
    conv_main<<<grid, 256>>>(bias, out);
}